// round 2
// baseline (speedup 1.0000x reference)
#include <cuda_runtime.h>

#define N_NODES 100000
#define DIM 128
#define NCLS 40
#define E_CAP 1600000

// ---------------- scratch (device globals — no allocation allowed) ----------
__device__ float g_agg[(size_t)N_NODES * DIM];    // mean-aggregated x
__device__ float g_h[(size_t)N_NODES * DIM];      // hidden activations
__device__ float g_q[(size_t)N_NODES * NCLS];     // h @ W2_l (pre-aggregation)
__device__ float g_r[(size_t)N_NODES * NCLS];     // h @ W2_r (root term)
__device__ float g_agg2[(size_t)N_NODES * NCLS];  // mean-aggregated q
__device__ float g_inv_deg[N_NODES];
__device__ int   g_deg[N_NODES];
__device__ int   g_fill[N_NODES];
__device__ int   g_row_ptr[N_NODES + 1];
__device__ int   g_col[E_CAP];
__device__ int   g_is64;

// ---------------- dtype detection -------------------------------------------
// edge_index is nominally int64 in the reference, but JAX without x64 silently
// produces int32. Detect at runtime: int64 little-endian indices < 2^31 have
// high word == 0 at every odd int32 position.
__global__ void k_detect(const int* __restrict__ ei32) {
    if (threadIdx.x == 0 && blockIdx.x == 0) {
        int is64 = 1;
        for (int i = 0; i < 64; i++)
            if (ei32[2 * i + 1] != 0) { is64 = 0; break; }
        g_is64 = is64;
    }
}

__device__ __forceinline__ int load_idx(const int* ei32, size_t elem, int is64) {
    return is64 ? ei32[2 * elem] : ei32[elem];
}

// ---------------- CSR build --------------------------------------------------
__global__ void k_zero_deg() {
    int i = blockIdx.x * blockDim.x + threadIdx.x;
    if (i < N_NODES) { g_deg[i] = 0; g_fill[i] = 0; }
}

__global__ void k_hist(const int* __restrict__ ei32, int E) {
    int e = blockIdx.x * blockDim.x + threadIdx.x;
    if (e < E) {
        int d = load_idx(ei32, (size_t)E + e, g_is64);   // dst
        if (d >= 0 && d < N_NODES) atomicAdd(&g_deg[d], 1);
    }
}

// Single-block exclusive scan of g_deg -> g_row_ptr, plus inv_deg.
__global__ void k_scan_block() {
    __shared__ int part[1024];
    const int t = threadIdx.x;
    const int chunk = (N_NODES + 1023) / 1024;   // 98
    int beg = t * chunk;
    int end = min(beg + chunk, N_NODES);
    int s = 0;
    for (int i = beg; i < end; i++) s += g_deg[i];
    part[t] = s;
    __syncthreads();
    // inclusive Hillis-Steele scan over 1024 partials
    for (int off = 1; off < 1024; off <<= 1) {
        int v = (t >= off) ? part[t - off] : 0;
        __syncthreads();
        part[t] += v;
        __syncthreads();
    }
    int run = (t > 0) ? part[t - 1] : 0;
    for (int i = beg; i < end; i++) {
        g_row_ptr[i] = run;
        int d = g_deg[i];
        run += d;
        g_inv_deg[i] = 1.0f / (float)max(d, 1);
    }
    if (t == 1023) g_row_ptr[N_NODES] = part[1023];
}

__global__ void k_scatter(const int* __restrict__ ei32, int E) {
    int e = blockIdx.x * blockDim.x + threadIdx.x;
    if (e < E) {
        int is64 = g_is64;
        int d = load_idx(ei32, (size_t)E + e, is64);
        int s = load_idx(ei32, (size_t)e, is64);
        if (d >= 0 && d < N_NODES && s >= 0 && s < N_NODES) {
            int pos = g_row_ptr[d] + atomicAdd(&g_fill[d], 1);
            if (pos >= 0 && pos < E_CAP) g_col[pos] = s;
        }
    }
}

// ---------------- aggregation: warp per node, D=128 --------------------------
__global__ void k_agg128(const float* __restrict__ feat) {
    int gid = blockIdx.x * blockDim.x + threadIdx.x;
    int node = gid >> 5;
    if (node >= N_NODES) return;
    int lane = gid & 31;
    int beg = g_row_ptr[node], end = g_row_ptr[node + 1];

    float4 acc = make_float4(0.f, 0.f, 0.f, 0.f);
    int j = beg;
    for (; j + 2 <= end; j += 2) {         // 2-way MLP
        int s0 = g_col[j], s1 = g_col[j + 1];
        float4 v0 = __ldg(((const float4*)(feat + (size_t)s0 * DIM)) + lane);
        float4 v1 = __ldg(((const float4*)(feat + (size_t)s1 * DIM)) + lane);
        acc.x += v0.x + v1.x; acc.y += v0.y + v1.y;
        acc.z += v0.z + v1.z; acc.w += v0.w + v1.w;
    }
    if (j < end) {
        int s0 = g_col[j];
        float4 v0 = __ldg(((const float4*)(feat + (size_t)s0 * DIM)) + lane);
        acc.x += v0.x; acc.y += v0.y; acc.z += v0.z; acc.w += v0.w;
    }
    float sc = g_inv_deg[node];
    acc.x *= sc; acc.y *= sc; acc.z *= sc; acc.w *= sc;
    *((float4*)(g_agg + (size_t)node * DIM) + lane) = acc;
}

// ---------------- layer 1: h = relu(agg@W1_l + x@W1_r + b1) -------------------
// block: 128 threads, tile 16 rows x 128 cols; thread = 4 rows x 4 cols.
__global__ void k_layer1(const float* __restrict__ x,
                         const float* __restrict__ W1l,
                         const float* __restrict__ b1,
                         const float* __restrict__ W1r) {
    __shared__ float sa[16][DIM];
    __shared__ float sx[16][DIM];
    const int row0 = blockIdx.x * 16;
    const int tid = threadIdx.x;

    // cooperative tile load: 16*128 floats = 512 float4s, 128 threads
    {
        const float4* ga = (const float4*)(g_agg + (size_t)row0 * DIM);
        const float4* gx = (const float4*)(x + (size_t)row0 * DIM);
        float4* la = (float4*)&sa[0][0];
        float4* lx = (float4*)&sx[0][0];
        #pragma unroll
        for (int i = 0; i < 4; i++) {
            la[tid + i * 128] = ga[tid + i * 128];
            lx[tid + i * 128] = gx[tid + i * 128];
        }
    }
    __syncthreads();

    const int c0 = (tid & 31) * 4;
    const int rb = (tid >> 5) * 4;

    float acc[4][4];
    {
        float4 bb = __ldg((const float4*)(b1 + c0));
        #pragma unroll
        for (int ri = 0; ri < 4; ri++) {
            acc[ri][0] = bb.x; acc[ri][1] = bb.y; acc[ri][2] = bb.z; acc[ri][3] = bb.w;
        }
    }

    #pragma unroll 4
    for (int k = 0; k < DIM; k++) {
        float4 wl = __ldg((const float4*)(W1l + (size_t)k * DIM + c0));
        float4 wr = __ldg((const float4*)(W1r + (size_t)k * DIM + c0));
        #pragma unroll
        for (int ri = 0; ri < 4; ri++) {
            float a = sa[rb + ri][k];
            float xv = sx[rb + ri][k];
            acc[ri][0] += a * wl.x + xv * wr.x;
            acc[ri][1] += a * wl.y + xv * wr.y;
            acc[ri][2] += a * wl.z + xv * wr.z;
            acc[ri][3] += a * wl.w + xv * wr.w;
        }
    }

    #pragma unroll
    for (int ri = 0; ri < 4; ri++) {
        float4 o;
        o.x = fmaxf(acc[ri][0], 0.f);
        o.y = fmaxf(acc[ri][1], 0.f);
        o.z = fmaxf(acc[ri][2], 0.f);
        o.w = fmaxf(acc[ri][3], 0.f);
        *((float4*)(g_h + (size_t)(row0 + rb + ri) * DIM + c0)) = o;
    }
}

// ---------------- layer 2 projections: q = h@W2_l, r = h@W2_r -----------------
// block: 320 threads, tile 16 rows. t%80 -> output col (0..39 q, 40..79 r),
// t/80 -> row group of 4.
__global__ void k_layer2(const float* __restrict__ W2l,
                         const float* __restrict__ W2r) {
    __shared__ float sh[16][DIM];
    const int row0 = blockIdx.x * 16;
    const int t = threadIdx.x;

    {
        const float4* gh = (const float4*)(g_h + (size_t)row0 * DIM);
        float4* ls = (float4*)&sh[0][0];
        for (int i = t; i < 512; i += 320) ls[i] = gh[i];
    }
    __syncthreads();

    const int oc = t % 80;
    const int rg = (t / 80) * 4;
    const bool is_l = (oc < NCLS);
    const int c = is_l ? oc : oc - NCLS;
    const float* W = is_l ? W2l : W2r;

    float a0 = 0.f, a1 = 0.f, a2 = 0.f, a3 = 0.f;
    #pragma unroll 8
    for (int k = 0; k < DIM; k++) {
        float w = __ldg(W + (size_t)k * NCLS + c);
        a0 += sh[rg + 0][k] * w;
        a1 += sh[rg + 1][k] * w;
        a2 += sh[rg + 2][k] * w;
        a3 += sh[rg + 3][k] * w;
    }
    float* outp = is_l ? g_q : g_r;
    outp[(size_t)(row0 + rg + 0) * NCLS + c] = a0;
    outp[(size_t)(row0 + rg + 1) * NCLS + c] = a1;
    outp[(size_t)(row0 + rg + 2) * NCLS + c] = a2;
    outp[(size_t)(row0 + rg + 3) * NCLS + c] = a3;
}

// ---------------- aggregation of q (40-dim), warp per node --------------------
__global__ void k_agg40() {
    int gid = blockIdx.x * blockDim.x + threadIdx.x;
    int node = gid >> 5;
    if (node >= N_NODES) return;
    int lane = gid & 31;
    int beg = g_row_ptr[node], end = g_row_ptr[node + 1];

    float acc0 = 0.f, acc1 = 0.f;
    for (int j = beg; j < end; j++) {
        int s = g_col[j];
        const float* row = g_q + (size_t)s * NCLS;
        acc0 += __ldg(row + lane);
        if (lane < 8) acc1 += __ldg(row + 32 + lane);
    }
    float sc = g_inv_deg[node];
    g_agg2[(size_t)node * NCLS + lane] = acc0 * sc;
    if (lane < 8) g_agg2[(size_t)node * NCLS + 32 + lane] = acc1 * sc;
}

// ---------------- final: out = log_softmax(agg2 + r + b2) ---------------------
__global__ void k_final(const float* __restrict__ b2, float* __restrict__ out) {
    int gid = blockIdx.x * blockDim.x + threadIdx.x;
    int node = gid >> 5;
    if (node >= N_NODES) return;
    int lane = gid & 31;

    const size_t base = (size_t)node * NCLS;
    float va = g_agg2[base + lane] + g_r[base + lane] + __ldg(b2 + lane);
    float vb = -1e30f;
    if (lane < 8)
        vb = g_agg2[base + 32 + lane] + g_r[base + 32 + lane] + __ldg(b2 + 32 + lane);

    float m = fmaxf(va, vb);
    #pragma unroll
    for (int off = 16; off > 0; off >>= 1)
        m = fmaxf(m, __shfl_xor_sync(0xffffffffu, m, off));

    float s = expf(va - m) + ((lane < 8) ? expf(vb - m) : 0.f);
    #pragma unroll
    for (int off = 16; off > 0; off >>= 1)
        s += __shfl_xor_sync(0xffffffffu, s, off);

    float lse = m + logf(s);
    out[base + lane] = va - lse;
    if (lane < 8) out[base + 32 + lane] = vb - lse;
}

// ---------------- launch -----------------------------------------------------
extern "C" void kernel_launch(void* const* d_in, const int* in_sizes, int n_in,
                              void* d_out, int out_size) {
    const float* x   = (const float*)d_in[0];
    const int*   ei  = (const int*)d_in[1];       // int32 OR int64 (detected)
    const float* W1l = (const float*)d_in[2];
    const float* b1  = (const float*)d_in[3];
    const float* W1r = (const float*)d_in[4];
    const float* W2l = (const float*)d_in[5];
    const float* b2  = (const float*)d_in[6];
    const float* W2r = (const float*)d_in[7];
    float* out = (float*)d_out;

    const int E = in_sizes[1] / 2;   // element count / 2 rows, same for both dtypes

    k_detect<<<1, 32>>>(ei);
    k_zero_deg<<<(N_NODES + 255) / 256, 256>>>();
    k_hist<<<(E + 255) / 256, 256>>>(ei, E);
    k_scan_block<<<1, 1024>>>();
    k_scatter<<<(E + 255) / 256, 256>>>(ei, E);

    const int agg_blocks = (N_NODES * 32 + 255) / 256;
    k_agg128<<<agg_blocks, 256>>>(x);
    k_layer1<<<N_NODES / 16, 128>>>(x, W1l, b1, W1r);
    k_layer2<<<N_NODES / 16, 320>>>(W2l, W2r);
    k_agg40<<<agg_blocks, 256>>>();
    k_final<<<agg_blocks, 256>>>(b2, out);
}

// round 3
// speedup vs baseline: 1.2702x; 1.2702x over previous
#include <cuda_runtime.h>

#define N_NODES 100000
#define DIM 128
#define NCLS 40
#define E_CAP 1600000
#define SCAN_ELEMS 1024
#define SCAN_BLOCKS ((N_NODES + SCAN_ELEMS - 1) / SCAN_ELEMS)   // 98

// ---------------- scratch (device globals — no allocation allowed) ----------
__device__ float g_agg[(size_t)N_NODES * DIM];    // mean-aggregated x
__device__ float g_h[(size_t)N_NODES * DIM];      // hidden activations
__device__ float g_q[(size_t)N_NODES * NCLS];     // h @ W2_l (pre-aggregation)
__device__ float g_r[(size_t)N_NODES * NCLS];     // h @ W2_r (root term)
__device__ float g_agg2[(size_t)N_NODES * NCLS];  // mean-aggregated q
__device__ float g_inv_deg[N_NODES];
__device__ int   g_deg[N_NODES];
__device__ int   g_fill[N_NODES];
__device__ int   g_row_ptr[N_NODES + 1];
__device__ int   g_col[E_CAP];
__device__ int   g_bsum[SCAN_BLOCKS];
__device__ int   g_boff[SCAN_BLOCKS];
__device__ int   g_is64;

// ---------------- f32x2 helpers ----------------------------------------------
typedef unsigned long long ull;

__device__ __forceinline__ ull pk2(float lo, float hi) {
    ull r; asm("mov.b64 %0, {%1, %2};" : "=l"(r) : "f"(lo), "f"(hi)); return r;
}
__device__ __forceinline__ void upk2(ull v, float& lo, float& hi) {
    asm("mov.b64 {%0, %1}, %2;" : "=f"(lo), "=f"(hi) : "l"(v));
}
__device__ __forceinline__ ull fma2(ull a, ull b, ull c) {
    ull d; asm("fma.rn.f32x2 %0, %1, %2, %3;" : "=l"(d) : "l"(a), "l"(b), "l"(c)); return d;
}

// ---------------- dtype detection -------------------------------------------
// edge_index is nominally int64, but JAX without x64 silently emits int32.
// int64 LE indices < 2^31 have zero high words at every odd int32 position.
__global__ void k_detect(const int* __restrict__ ei32) {
    if (threadIdx.x == 0 && blockIdx.x == 0) {
        int is64 = 1;
        for (int i = 0; i < 64; i++)
            if (ei32[2 * i + 1] != 0) { is64 = 0; break; }
        g_is64 = is64;
    }
}

__device__ __forceinline__ int load_idx(const int* ei32, size_t elem, int is64) {
    return is64 ? ei32[2 * elem] : ei32[elem];
}

// ---------------- CSR build --------------------------------------------------
__global__ void k_zero_deg() {
    int i = blockIdx.x * blockDim.x + threadIdx.x;
    if (i < N_NODES) { g_deg[i] = 0; g_fill[i] = 0; }
}

__global__ void k_hist(const int* __restrict__ ei32, int E) {
    int e = blockIdx.x * blockDim.x + threadIdx.x;
    if (e < E) {
        int d = load_idx(ei32, (size_t)E + e, g_is64);   // dst
        if (d >= 0 && d < N_NODES) atomicAdd(&g_deg[d], 1);
    }
}

// Phase 1: per-block exclusive scan of 1024 elements (256 thr x 4), block sums out.
__global__ void k_blockscan() {
    __shared__ int wsum[8];
    const int t = threadIdx.x;
    const int lane = t & 31, wid = t >> 5;
    const int base = blockIdx.x * SCAN_ELEMS + t * 4;

    int4 d = make_int4(0, 0, 0, 0);
    if (base + 3 < N_NODES) {
        d = *(const int4*)&g_deg[base];
    } else {
        int v[4] = {0, 0, 0, 0};
        for (int i = 0; i < 4; i++) if (base + i < N_NODES) v[i] = g_deg[base + i];
        d = make_int4(v[0], v[1], v[2], v[3]);
    }
    int s = d.x + d.y + d.z + d.w;

    int incl = s;
    #pragma unroll
    for (int off = 1; off < 32; off <<= 1) {
        int v = __shfl_up_sync(0xffffffffu, incl, off);
        if (lane >= off) incl += v;
    }
    if (lane == 31) wsum[wid] = incl;
    __syncthreads();
    if (wid == 0) {
        int v = (lane < 8) ? wsum[lane] : 0;
        #pragma unroll
        for (int off = 1; off < 8; off <<= 1) {
            int u = __shfl_up_sync(0xffffffffu, v, off);
            if (lane >= off) v += u;
        }
        if (lane < 8) wsum[lane] = v;   // inclusive over warps
    }
    __syncthreads();

    int excl = incl - s + ((wid > 0) ? wsum[wid - 1] : 0);
    if (base < N_NODES) {
        int r0 = excl, r1 = r0 + d.x, r2 = r1 + d.y, r3 = r2 + d.z;
        if (base + 3 < N_NODES) {
            *(int4*)&g_row_ptr[base] = make_int4(r0, r1, r2, r3);
        } else {
            int r[4] = {r0, r1, r2, r3};
            for (int i = 0; i < 4; i++) if (base + i < N_NODES) g_row_ptr[base + i] = r[i];
        }
    }
    if (t == 255) g_bsum[blockIdx.x] = wsum[7];
}

// Phase 2: scan the 98 block sums (1 small block).
__global__ void k_bsum_scan() {
    __shared__ int ws[4];
    const int t = threadIdx.x, lane = t & 31, wid = t >> 5;   // 128 threads
    int v = (t < SCAN_BLOCKS) ? g_bsum[t] : 0;
    int incl = v;
    #pragma unroll
    for (int off = 1; off < 32; off <<= 1) {
        int u = __shfl_up_sync(0xffffffffu, incl, off);
        if (lane >= off) incl += u;
    }
    if (lane == 31) ws[wid] = incl;
    __syncthreads();
    if (wid == 0) {
        int u = (lane < 4) ? ws[lane] : 0;
        #pragma unroll
        for (int off = 1; off < 4; off <<= 1) {
            int w = __shfl_up_sync(0xffffffffu, u, off);
            if (lane >= off) u += w;
        }
        if (lane < 4) ws[lane] = u;
    }
    __syncthreads();
    int excl = incl - v + ((wid > 0) ? ws[wid - 1] : 0);
    if (t < SCAN_BLOCKS) g_boff[t] = excl;
    if (t == 127) g_row_ptr[N_NODES] = ws[3];   // total edge count
}

// Phase 3: add block offsets; also compute inv_deg.
__global__ void k_addoff() {
    const int t = threadIdx.x;
    const int base = blockIdx.x * SCAN_ELEMS + t * 4;
    const int off = g_boff[blockIdx.x];
    #pragma unroll
    for (int i = 0; i < 4; i++) {
        int idx = base + i;
        if (idx < N_NODES) {
            g_row_ptr[idx] += off;
            int dg = g_deg[idx];
            g_inv_deg[idx] = 1.0f / (float)max(dg, 1);
        }
    }
}

__global__ void k_scatter(const int* __restrict__ ei32, int E) {
    int e = blockIdx.x * blockDim.x + threadIdx.x;
    if (e < E) {
        int is64 = g_is64;
        int d = load_idx(ei32, (size_t)E + e, is64);
        int s = load_idx(ei32, (size_t)e, is64);
        if (d >= 0 && d < N_NODES && s >= 0 && s < N_NODES) {
            int pos = g_row_ptr[d] + atomicAdd(&g_fill[d], 1);
            if (pos >= 0 && pos < E_CAP) g_col[pos] = s;
        }
    }
}

// ---------------- aggregation: warp per node, D=128 --------------------------
__global__ void k_agg128(const float* __restrict__ feat) {
    int gid = blockIdx.x * blockDim.x + threadIdx.x;
    int node = gid >> 5;
    if (node >= N_NODES) return;
    int lane = gid & 31;
    int beg = g_row_ptr[node], end = g_row_ptr[node + 1];

    float4 acc = make_float4(0.f, 0.f, 0.f, 0.f);
    int j = beg;
    for (; j + 2 <= end; j += 2) {
        int s0 = g_col[j], s1 = g_col[j + 1];
        float4 v0 = __ldg(((const float4*)(feat + (size_t)s0 * DIM)) + lane);
        float4 v1 = __ldg(((const float4*)(feat + (size_t)s1 * DIM)) + lane);
        acc.x += v0.x + v1.x; acc.y += v0.y + v1.y;
        acc.z += v0.z + v1.z; acc.w += v0.w + v1.w;
    }
    if (j < end) {
        int s0 = g_col[j];
        float4 v0 = __ldg(((const float4*)(feat + (size_t)s0 * DIM)) + lane);
        acc.x += v0.x; acc.y += v0.y; acc.z += v0.z; acc.w += v0.w;
    }
    float sc = g_inv_deg[node];
    acc.x *= sc; acc.y *= sc; acc.z *= sc; acc.w *= sc;
    *((float4*)(g_agg + (size_t)node * DIM) + lane) = acc;
}

// ---------------- layer 1: h = relu(agg@W1_l + x@W1_r + b1) -------------------
// 128 threads, tile 16 rows x 128 cols; thread = 4 rows x 4 cols.
// A/X tiles stored DUPLICATED in smem ({a,a} per k) so one broadcast LDS.64
// feeds fma.rn.f32x2 directly (no repack MOVs). Weights reinterpreted as
// 64-bit halves of the LDG.128 — free.
__global__ void k_layer1(const float* __restrict__ x,
                         const float* __restrict__ W1l,
                         const float* __restrict__ b1,
                         const float* __restrict__ W1r) {
    __shared__ ull sad[16][DIM];   // sad[row][k] = {a, a}
    __shared__ ull sxd[16][DIM];   // sxd[row][k] = {x, x}
    const int row0 = blockIdx.x * 16;
    const int tid = threadIdx.x;

    // load + duplicate: 512 float4s per tile, 128 threads x 4
    {
        const float4* ga = (const float4*)(g_agg + (size_t)row0 * DIM);
        const float4* gx = (const float4*)(x + (size_t)row0 * DIM);
        #pragma unroll
        for (int i = 0; i < 4; i++) {
            int idx = tid + i * 128;           // float4 linear index
            int row = idx >> 5;                // 32 float4 per row
            int c = (idx & 31) * 4;            // starting k
            float4 va = ga[idx];
            float4 vx = gx[idx];
            float4* da = (float4*)&sad[row][c];
            da[0] = make_float4(va.x, va.x, va.y, va.y);
            da[1] = make_float4(va.z, va.z, va.w, va.w);
            float4* dx = (float4*)&sxd[row][c];
            dx[0] = make_float4(vx.x, vx.x, vx.y, vx.y);
            dx[1] = make_float4(vx.z, vx.z, vx.w, vx.w);
        }
    }
    __syncthreads();

    const int c0 = (tid & 31) * 4;
    const int rb = (tid >> 5) * 4;

    ull acc[4][2];
    {
        float4 bb = __ldg((const float4*)(b1 + c0));
        ull b01 = pk2(bb.x, bb.y), b23 = pk2(bb.z, bb.w);
        #pragma unroll
        for (int ri = 0; ri < 4; ri++) { acc[ri][0] = b01; acc[ri][1] = b23; }
    }

    #pragma unroll 4
    for (int k = 0; k < DIM; k++) {
        ulonglong2 wl = __ldg((const ulonglong2*)(W1l + (size_t)k * DIM + c0));
        ulonglong2 wr = __ldg((const ulonglong2*)(W1r + (size_t)k * DIM + c0));
        #pragma unroll
        for (int ri = 0; ri < 4; ri++) {
            ull a  = sad[rb + ri][k];   // broadcast LDS.64: {a,a}
            ull xv = sxd[rb + ri][k];   // {x,x}
            acc[ri][0] = fma2(a,  wl.x, acc[ri][0]);
            acc[ri][1] = fma2(a,  wl.y, acc[ri][1]);
            acc[ri][0] = fma2(xv, wr.x, acc[ri][0]);
            acc[ri][1] = fma2(xv, wr.y, acc[ri][1]);
        }
    }

    #pragma unroll
    for (int ri = 0; ri < 4; ri++) {
        float o0, o1, o2, o3;
        upk2(acc[ri][0], o0, o1);
        upk2(acc[ri][1], o2, o3);
        float4 o;
        o.x = fmaxf(o0, 0.f); o.y = fmaxf(o1, 0.f);
        o.z = fmaxf(o2, 0.f); o.w = fmaxf(o3, 0.f);
        *((float4*)(g_h + (size_t)(row0 + rb + ri) * DIM + c0)) = o;
    }
}

// ---------------- layer 2 projections: q = h@W2_l, r = h@W2_r -----------------
__global__ void k_layer2(const float* __restrict__ W2l,
                         const float* __restrict__ W2r) {
    __shared__ float sh[16][DIM];
    const int row0 = blockIdx.x * 16;
    const int t = threadIdx.x;

    {
        const float4* gh = (const float4*)(g_h + (size_t)row0 * DIM);
        float4* ls = (float4*)&sh[0][0];
        for (int i = t; i < 512; i += 320) ls[i] = gh[i];
    }
    __syncthreads();

    const int oc = t % 80;
    const int rg = (t / 80) * 4;
    const bool is_l = (oc < NCLS);
    const int c = is_l ? oc : oc - NCLS;
    const float* W = is_l ? W2l : W2r;

    float a0 = 0.f, a1 = 0.f, a2 = 0.f, a3 = 0.f;
    #pragma unroll 8
    for (int k = 0; k < DIM; k++) {
        float w = __ldg(W + (size_t)k * NCLS + c);
        a0 += sh[rg + 0][k] * w;
        a1 += sh[rg + 1][k] * w;
        a2 += sh[rg + 2][k] * w;
        a3 += sh[rg + 3][k] * w;
    }
    float* outp = is_l ? g_q : g_r;
    outp[(size_t)(row0 + rg + 0) * NCLS + c] = a0;
    outp[(size_t)(row0 + rg + 1) * NCLS + c] = a1;
    outp[(size_t)(row0 + rg + 2) * NCLS + c] = a2;
    outp[(size_t)(row0 + rg + 3) * NCLS + c] = a3;
}

// ---------------- aggregation of q (40-dim), warp per node --------------------
__global__ void k_agg40() {
    int gid = blockIdx.x * blockDim.x + threadIdx.x;
    int node = gid >> 5;
    if (node >= N_NODES) return;
    int lane = gid & 31;
    int beg = g_row_ptr[node], end = g_row_ptr[node + 1];

    float acc0 = 0.f, acc1 = 0.f;
    for (int j = beg; j < end; j++) {
        int s = g_col[j];
        const float* row = g_q + (size_t)s * NCLS;
        acc0 += __ldg(row + lane);
        if (lane < 8) acc1 += __ldg(row + 32 + lane);
    }
    float sc = g_inv_deg[node];
    g_agg2[(size_t)node * NCLS + lane] = acc0 * sc;
    if (lane < 8) g_agg2[(size_t)node * NCLS + 32 + lane] = acc1 * sc;
}

// ---------------- final: out = log_softmax(agg2 + r + b2) ---------------------
__global__ void k_final(const float* __restrict__ b2, float* __restrict__ out) {
    int gid = blockIdx.x * blockDim.x + threadIdx.x;
    int node = gid >> 5;
    if (node >= N_NODES) return;
    int lane = gid & 31;

    const size_t base = (size_t)node * NCLS;
    float va = g_agg2[base + lane] + g_r[base + lane] + __ldg(b2 + lane);
    float vb = -1e30f;
    if (lane < 8)
        vb = g_agg2[base + 32 + lane] + g_r[base + 32 + lane] + __ldg(b2 + 32 + lane);

    float m = fmaxf(va, vb);
    #pragma unroll
    for (int off = 16; off > 0; off >>= 1)
        m = fmaxf(m, __shfl_xor_sync(0xffffffffu, m, off));

    float s = expf(va - m) + ((lane < 8) ? expf(vb - m) : 0.f);
    #pragma unroll
    for (int off = 16; off > 0; off >>= 1)
        s += __shfl_xor_sync(0xffffffffu, s, off);

    float lse = m + logf(s);
    out[base + lane] = va - lse;
    if (lane < 8) out[base + 32 + lane] = vb - lse;
}

// ---------------- launch -----------------------------------------------------
extern "C" void kernel_launch(void* const* d_in, const int* in_sizes, int n_in,
                              void* d_out, int out_size) {
    const float* x   = (const float*)d_in[0];
    const int*   ei  = (const int*)d_in[1];       // int32 OR int64 (detected)
    const float* W1l = (const float*)d_in[2];
    const float* b1  = (const float*)d_in[3];
    const float* W1r = (const float*)d_in[4];
    const float* W2l = (const float*)d_in[5];
    const float* b2  = (const float*)d_in[6];
    const float* W2r = (const float*)d_in[7];
    float* out = (float*)d_out;

    const int E = in_sizes[1] / 2;

    k_detect<<<1, 32>>>(ei);
    k_zero_deg<<<(N_NODES + 255) / 256, 256>>>();
    k_hist<<<(E + 255) / 256, 256>>>(ei, E);
    k_blockscan<<<SCAN_BLOCKS, 256>>>();
    k_bsum_scan<<<1, 128>>>();
    k_addoff<<<SCAN_BLOCKS, 256>>>();
    k_scatter<<<(E + 255) / 256, 256>>>(ei, E);

    const int agg_blocks = (N_NODES * 32 + 255) / 256;
    k_agg128<<<agg_blocks, 256>>>(x);
    k_layer1<<<N_NODES / 16, 128>>>(x, W1l, b1, W1r);
    k_layer2<<<N_NODES / 16, 320>>>(W2l, W2r);
    k_agg40<<<agg_blocks, 256>>>();
    k_final<<<agg_blocks, 256>>>(b2, out);
}